// round 2
// baseline (speedup 1.0000x reference)
#include <cuda_runtime.h>
#include <cuda_bf16.h>
#include <cstdint>

#define T_STEPS 4096
#define ISZ 512
#define HSZ 2048
#define GSZ (4*HSZ)          // 8192 gate rows
#define NBLK 148             // persistent CTAs (<= SM count)
#define NTHR 512

// ---------------- static device scratch (no allocations allowed) ------------
__device__ float g_X[(size_t)T_STEPS * GSZ];   // precomputed input gates, 134 MB
__device__ float g_h[2][HSZ];                  // double-buffered hidden state
__device__ unsigned g_count = 0;               // grid barrier counter (self-resetting)
__device__ unsigned g_gen = 0;                 // grid barrier generation (monotonic)

// ---------------- grid barrier (all CTAs resident by construction) ----------
__device__ __forceinline__ void grid_barrier(unsigned nb) {
    __syncthreads();
    if (threadIdx.x == 0) {
        volatile unsigned* vgen = &g_gen;
        unsigned my = *vgen;
        __threadfence();                       // release prior global writes
        unsigned prev = atomicAdd(&g_count, 1u);
        if (prev == nb - 1u) {
            g_count = 0u;
            __threadfence();
            *vgen = my + 1u;
        } else {
            while (*vgen == my) { }
        }
        __threadfence();                       // acquire
    }
    __syncthreads();
}

// ====================== Kernel 1: X = input @ W_ih^T + (b_ih+b_hh) ==========
// C[M=T_STEPS, N=GSZ] ; A=input[T,ISZ] row-major ; B=W_ih[GSZ,ISZ] row-major
#define BM 128
#define BN 128
#define BK 16

__global__ void __launch_bounds__(256) gemm_xgates(
    const float* __restrict__ A, const float* __restrict__ B,
    const float* __restrict__ b_ih, const float* __restrict__ b_hh)
{
    __shared__ float As[BK][BM];
    __shared__ float Bs[BK][BN];
    const int tid = threadIdx.x;
    const int tx = tid & 15, ty = tid >> 4;
    const int m0 = blockIdx.y * BM, n0 = blockIdx.x * BN;
    float acc[8][8] = {};

    for (int k0 = 0; k0 < ISZ; k0 += BK) {
        #pragma unroll
        for (int rep = 0; rep < 2; rep++) {
            int row = (tid >> 2) + rep * 64;
            int kg  = (tid & 3) * 4;
            float4 va = *(const float4*)&A[(size_t)(m0 + row) * ISZ + k0 + kg];
            As[kg+0][row] = va.x; As[kg+1][row] = va.y;
            As[kg+2][row] = va.z; As[kg+3][row] = va.w;
            float4 vb = *(const float4*)&B[(size_t)(n0 + row) * ISZ + k0 + kg];
            Bs[kg+0][row] = vb.x; Bs[kg+1][row] = vb.y;
            Bs[kg+2][row] = vb.z; Bs[kg+3][row] = vb.w;
        }
        __syncthreads();
        #pragma unroll
        for (int kk = 0; kk < BK; kk++) {
            float a[8], b[8];
            float4 a0 = *(const float4*)&As[kk][ty * 8];
            float4 a1 = *(const float4*)&As[kk][ty * 8 + 4];
            float4 b0 = *(const float4*)&Bs[kk][tx * 8];
            float4 b1 = *(const float4*)&Bs[kk][tx * 8 + 4];
            a[0]=a0.x; a[1]=a0.y; a[2]=a0.z; a[3]=a0.w;
            a[4]=a1.x; a[5]=a1.y; a[6]=a1.z; a[7]=a1.w;
            b[0]=b0.x; b[1]=b0.y; b[2]=b0.z; b[3]=b0.w;
            b[4]=b1.x; b[5]=b1.y; b[6]=b1.z; b[7]=b1.w;
            #pragma unroll
            for (int i = 0; i < 8; i++)
                #pragma unroll
                for (int j = 0; j < 8; j++)
                    acc[i][j] += a[i] * b[j];
        }
        __syncthreads();
    }
    #pragma unroll
    for (int i = 0; i < 8; i++) {
        int m = m0 + ty * 8 + i;
        #pragma unroll
        for (int j = 0; j < 8; j++) {
            int n = n0 + tx * 8 + j;
            g_X[(size_t)m * GSZ + n] = acc[i][j] + b_ih[n] + b_hh[n];
        }
    }
}

// ====================== Kernel 2: persistent recurrence =====================
// Each CTA owns U hidden units (U=14 for CTAs 0..123, U=13 for 124..147),
// i.e. R=4U gate rows of W_hh held bf16-packed in SMEM for all 4096 steps.
// Warp layout: 16 warps = 2 K-halves x 8 row-slots. Lane holds its 32-float
// h slice in registers; per row: 4x LDS.128 + unpack + FFMA, warp-reduce,
// smem atomicAdd, then per-unit gate epilogue, h broadcast, grid barrier.

__device__ __forceinline__ float sigf(float x) { return 1.f / (1.f + __expf(-x)); }

__global__ void __launch_bounds__(NTHR) lstm_recurrent(const float* __restrict__ W_hh)
{
    extern __shared__ unsigned smem[];
    unsigned* sw  = smem;                          // [R][1024] bf16x2 weights
    float* sacc   = (float*)(smem + 56 * 1024);    // [R] gate partial sums

    const int b   = blockIdx.x;
    const int tid = threadIdx.x;
    const int U   = (b < 124) ? 14 : 13;
    const int u0  = (b < 124) ? b * 14 : 124 * 14 + (b - 124) * 13;
    const int R   = 4 * U;

    // ---- setup: stage W_hh slice as packed bf16 pairs in SMEM ----
    for (int idx = tid; idx < R * 1024; idx += NTHR) {
        int r  = idx >> 10;
        int k2 = idx & 1023;
        int grow = (r / U) * HSZ + u0 + (r % U);   // gate-major global row
        float2 w2 = *(const float2*)&W_hh[(size_t)grow * HSZ + 2 * k2];
        unsigned lo = (unsigned)__bfloat16_as_ushort(__float2bfloat16(w2.x));
        unsigned hi = (unsigned)__bfloat16_as_ushort(__float2bfloat16(w2.y));
        sw[idx] = (hi << 16) | lo;
    }
    float c_state = 0.f;
    if (tid < U) { g_h[0][u0 + tid] = 0.f; g_h[1][u0 + tid] = 0.f; }
    if (tid < U) __threadfence();
    grid_barrier(NBLK);

    const int w = tid >> 5, l = tid & 31;
    const int khalf = w >> 3;        // which half of K this warp covers
    const int wr    = w & 7;         // row slot

    const uint4* wbase = (const uint4*)sw;

    for (int t = 0; t < T_STEPS; t++) {
        // -- load this warp's 1024-wide h slice into registers (L2, fresh) --
        float h[32];
        {
            const float4* hb = (const float4*)&g_h[t & 1][khalf * 1024];
            #pragma unroll
            for (int i = 0; i < 4; i++) {
                float4 ha = __ldcg(hb + i * 64 + l * 2);
                float4 hbv = __ldcg(hb + i * 64 + l * 2 + 1);
                h[i*8+0]=ha.x;  h[i*8+1]=ha.y;  h[i*8+2]=ha.z;  h[i*8+3]=ha.w;
                h[i*8+4]=hbv.x; h[i*8+5]=hbv.y; h[i*8+6]=hbv.z; h[i*8+7]=hbv.w;
            }
        }
        if (tid < R) sacc[tid] = 0.f;
        __syncthreads();

        // -- MAC phase --
        for (int r = wr; r < R; r += 8) {
            const uint4* wp = wbase + r * 256 + khalf * 128 + l;
            float acc0 = 0.f, acc1 = 0.f;
            #pragma unroll
            for (int i = 0; i < 4; i++) {
                uint4 wq = wp[i * 32];
                acc0 += __uint_as_float(wq.x << 16)          * h[i*8+0];
                acc1 += __uint_as_float(wq.x & 0xFFFF0000u)  * h[i*8+1];
                acc0 += __uint_as_float(wq.y << 16)          * h[i*8+2];
                acc1 += __uint_as_float(wq.y & 0xFFFF0000u)  * h[i*8+3];
                acc0 += __uint_as_float(wq.z << 16)          * h[i*8+4];
                acc1 += __uint_as_float(wq.z & 0xFFFF0000u)  * h[i*8+5];
                acc0 += __uint_as_float(wq.w << 16)          * h[i*8+6];
                acc1 += __uint_as_float(wq.w & 0xFFFF0000u)  * h[i*8+7];
            }
            float acc = acc0 + acc1;
            #pragma unroll
            for (int s = 16; s > 0; s >>= 1)
                acc += __shfl_xor_sync(0xffffffffu, acc, s);
            if (l == 0) atomicAdd(&sacc[r], acc);
        }
        __syncthreads();

        // -- epilogue: gates -> (c, h) for this CTA's units --
        if (tid < U) {
            const float* xg = &g_X[(size_t)t * GSZ];
            float gi = sacc[0*U + tid] + xg[            u0 + tid];
            float gf = sacc[1*U + tid] + xg[    HSZ +   u0 + tid];
            float gg = sacc[2*U + tid] + xg[2 * HSZ +   u0 + tid];
            float go = sacc[3*U + tid] + xg[3 * HSZ +   u0 + tid];
            float ig = sigf(gi);
            float fg = sigf(gf);
            float gt = tanhf(gg);
            float og = sigf(go);
            c_state = fg * c_state + ig * gt;
            float hv = og * tanhf(c_state);
            g_h[(t + 1) & 1][u0 + tid] = hv;
            __threadfence();
        }
        grid_barrier(NBLK);
    }
}

// ====================== Kernel 3: out = h_T @ W_lin^T + b_lin ===============
__global__ void __launch_bounds__(256) final_linear(
    const float* __restrict__ W_lin, const float* __restrict__ b_lin, float* out)
{
    __shared__ float red[256];
    float s = 0.f;
    // T_STEPS is even -> final h lives in buffer 0
    for (int k = threadIdx.x; k < HSZ; k += 256)
        s += g_h[0][k] * W_lin[k];
    red[threadIdx.x] = s;
    __syncthreads();
    for (int o = 128; o > 0; o >>= 1) {
        if (threadIdx.x < o) red[threadIdx.x] += red[threadIdx.x + o];
        __syncthreads();
    }
    if (threadIdx.x == 0) out[0] = red[0] + b_lin[0];
}

// ============================================================================
extern "C" void kernel_launch(void* const* d_in, const int* in_sizes, int n_in,
                              void* d_out, int out_size)
{
    const float* input = (const float*)d_in[0];
    const float* W_ih  = (const float*)d_in[1];
    const float* W_hh  = (const float*)d_in[2];
    const float* b_ih  = (const float*)d_in[3];
    const float* b_hh  = (const float*)d_in[4];
    const float* W_lin = (const float*)d_in[5];
    const float* b_lin = (const float*)d_in[6];

    // 1) precompute input-gate contributions
    dim3 g1(GSZ / BN, T_STEPS / BM);
    gemm_xgates<<<g1, 256>>>(input, W_ih, b_ih, b_hh);

    // 2) persistent recurrent kernel (weights resident in SMEM)
    const int smem_bytes = 56 * 1024 * 4 + 256;   // 229,376 weights + sacc
    cudaFuncSetAttribute(lstm_recurrent,
                         cudaFuncAttributeMaxDynamicSharedMemorySize, smem_bytes);
    lstm_recurrent<<<NBLK, NTHR, smem_bytes>>>(W_hh);

    // 3) final linear layer
    final_linear<<<1, 256>>>(W_lin, b_lin, (float*)d_out);
}

// round 4
// speedup vs baseline: 1.1980x; 1.1980x over previous
#include <cuda_runtime.h>
#include <cuda_bf16.h>
#include <cstdint>

#define T_STEPS 4096
#define ISZ 512
#define HSZ 2048
#define GSZ (4*HSZ)          // 8192 gate rows
#define NBLK 148             // persistent CTAs (1 per SM, forced by smem)
#define NTHR 512
#define RMAX 56              // padded gate rows per CTA (4*14)

// ---------------- static device scratch (no allocations allowed) ------------
__device__ float g_X[(size_t)T_STEPS * GSZ];   // precomputed input gates
__device__ float g_h[2][HSZ];                  // double-buffered hidden state
__device__ unsigned g_cnt[8 * 32];             // 8 arrival counters, 128B apart
__device__ unsigned g_go;                      // broadcast release stamp

// ---------------- morally-strong flag ops (PTX acquire/release, gpu scope) --
__device__ __forceinline__ void red_release_add(unsigned* p, unsigned v) {
    asm volatile("red.release.gpu.global.add.u32 [%0], %1;"
                 :: "l"(p), "r"(v) : "memory");
}
__device__ __forceinline__ unsigned ld_acquire(const unsigned* p) {
    unsigned v;
    asm volatile("ld.acquire.gpu.global.u32 %0, [%1];"
                 : "=r"(v) : "l"(p) : "memory");
    return v;
}
__device__ __forceinline__ void st_release(unsigned* p, unsigned v) {
    asm volatile("st.release.gpu.global.u32 [%0], %1;"
                 :: "l"(p), "r"(v) : "memory");
}

// Grid barrier: release-add arrival onto 8 spread counters (parallel LTS
// slices), CTA0 checker with acquire polls, single release word, acquire
// waiter polls. All flag ops are morally strong -> transitive visibility of
// prior h stores is guaranteed by the PTX memory model. Counters are
// monotonic (checker compares against stamp*group_size); reset happens in
// final_linear so graph replays are deterministic.
__device__ __forceinline__ void grid_barrier(int b, unsigned stamp) {
    __syncthreads();
    if (threadIdx.x == 0) {
        __threadfence();                         // order h stores before arrive
        red_release_add(&g_cnt[(b & 7) * 32], 1u);
    }
    if (b == 0) {
        if (threadIdx.x < 8) {
            const unsigned gsz  = (threadIdx.x < 4) ? 19u : 18u;  // 148 = 4*19+4*18
            const unsigned need = stamp * gsz;
            while (ld_acquire(&g_cnt[threadIdx.x * 32]) < need) { }
        }
        __syncthreads();
        if (threadIdx.x == 0) st_release(&g_go, stamp);
    }
    if (threadIdx.x == 0) {
        while (ld_acquire(&g_go) < stamp) { }
    }
    __syncthreads();
}

// ====================== Kernel 1: X = input @ W_ih^T + (b_ih+b_hh) ==========
#define BM 128
#define BN 128
#define BK 16

__global__ void __launch_bounds__(256) gemm_xgates(
    const float* __restrict__ A, const float* __restrict__ B,
    const float* __restrict__ b_ih, const float* __restrict__ b_hh)
{
    __shared__ float As[BK][BM];
    __shared__ float Bs[BK][BN];
    const int tid = threadIdx.x;
    const int tx = tid & 15, ty = tid >> 4;
    const int m0 = blockIdx.y * BM, n0 = blockIdx.x * BN;
    float acc[8][8] = {};

    for (int k0 = 0; k0 < ISZ; k0 += BK) {
        #pragma unroll
        for (int rep = 0; rep < 2; rep++) {
            int row = (tid >> 2) + rep * 64;
            int kg  = (tid & 3) * 4;
            float4 va = *(const float4*)&A[(size_t)(m0 + row) * ISZ + k0 + kg];
            As[kg+0][row] = va.x; As[kg+1][row] = va.y;
            As[kg+2][row] = va.z; As[kg+3][row] = va.w;
            float4 vb = *(const float4*)&B[(size_t)(n0 + row) * ISZ + k0 + kg];
            Bs[kg+0][row] = vb.x; Bs[kg+1][row] = vb.y;
            Bs[kg+2][row] = vb.z; Bs[kg+3][row] = vb.w;
        }
        __syncthreads();
        #pragma unroll
        for (int kk = 0; kk < BK; kk++) {
            float a[8], bb[8];
            float4 a0 = *(const float4*)&As[kk][ty * 8];
            float4 a1 = *(const float4*)&As[kk][ty * 8 + 4];
            float4 b0 = *(const float4*)&Bs[kk][tx * 8];
            float4 b1 = *(const float4*)&Bs[kk][tx * 8 + 4];
            a[0]=a0.x; a[1]=a0.y; a[2]=a0.z; a[3]=a0.w;
            a[4]=a1.x; a[5]=a1.y; a[6]=a1.z; a[7]=a1.w;
            bb[0]=b0.x; bb[1]=b0.y; bb[2]=b0.z; bb[3]=b0.w;
            bb[4]=b1.x; bb[5]=b1.y; bb[6]=b1.z; bb[7]=b1.w;
            #pragma unroll
            for (int i = 0; i < 8; i++)
                #pragma unroll
                for (int j = 0; j < 8; j++)
                    acc[i][j] += a[i] * bb[j];
        }
        __syncthreads();
    }
    #pragma unroll
    for (int i = 0; i < 8; i++) {
        int m = m0 + ty * 8 + i;
        #pragma unroll
        for (int j = 0; j < 8; j++) {
            int n = n0 + tx * 8 + j;
            g_X[(size_t)m * GSZ + n] = acc[i][j] + b_ih[n] + b_hh[n];
        }
    }
}

// ====================== Kernel 2: persistent recurrence =====================
__device__ __forceinline__ float sigf(float x) { return 1.f / (1.f + __expf(-x)); }

template<int U>
__device__ __forceinline__ void lstm_body(const int b, const int u0,
                                          const float* __restrict__ W_hh)
{
    constexpr int R = 4 * U;          // live gate rows (52 or 56)
    extern __shared__ unsigned smem[];
    unsigned* sw = smem;                              // [RMAX][1024] bf16x2
    float* sacc  = (float*)(smem + RMAX * 1024);      // [2][RMAX]

    const int tid = threadIdx.x;

    // ---- stage W_hh slice as packed bf16 pairs; pad rows >= R with zeros ----
    for (int idx = tid; idx < RMAX * 1024; idx += NTHR) {
        const int r  = idx >> 10;
        const int k2 = idx & 1023;
        unsigned packed = 0u;
        if (r < R) {
            const int grow = (r / U) * HSZ + u0 + (r % U);
            float2 w2 = *(const float2*)&W_hh[(size_t)grow * HSZ + 2 * k2];
            unsigned lo = (unsigned)__bfloat16_as_ushort(__float2bfloat16(w2.x));
            unsigned hi = (unsigned)__bfloat16_as_ushort(__float2bfloat16(w2.y));
            packed = (hi << 16) | lo;
        }
        sw[idx] = packed;
    }
    float c_state = 0.f;
    if (tid < U) g_h[0][u0 + tid] = 0.f;
    grid_barrier(b, 1u);              // publishes h zeros (fence inside)

    const int w = tid >> 5, l = tid & 31;
    const int khalf = w >> 3;         // K half this warp covers
    const int wr    = w & 7;          // row slot
    const uint4* wbase = (const uint4*)sw;

    for (int t = 0; t < T_STEPS; t++) {
        // -- prefetch this step's x-gate terms (DRAM latency hides under MAC)
        float xgi = 0.f, xgf = 0.f, xgg = 0.f, xgo = 0.f;
        if (tid < U) {
            const float* xg = &g_X[(size_t)t * GSZ + u0 + tid];
            xgi = __ldcs(xg);
            xgf = __ldcs(xg + HSZ);
            xgg = __ldcs(xg + 2 * HSZ);
            xgo = __ldcs(xg + 3 * HSZ);
        }

        // -- load this warp's 1024-wide h slice into registers (fresh from L2)
        float h[32];
        {
            const float4* hb = (const float4*)&g_h[t & 1][khalf * 1024];
            #pragma unroll
            for (int i = 0; i < 4; i++) {
                float4 ha = __ldcg(hb + i * 64 + l * 2);
                float4 hc = __ldcg(hb + i * 64 + l * 2 + 1);
                h[i*8+0]=ha.x; h[i*8+1]=ha.y; h[i*8+2]=ha.z; h[i*8+3]=ha.w;
                h[i*8+4]=hc.x; h[i*8+5]=hc.y; h[i*8+6]=hc.z; h[i*8+7]=hc.w;
            }
        }

        // -- MAC phase: 7 independent rows per warp, fully unrolled ----------
        #pragma unroll
        for (int rr = 0; rr < 7; rr++) {
            const int r = wr + rr * 8;
            const uint4* wp = wbase + r * 256 + khalf * 128 + l;
            float acc0 = 0.f, acc1 = 0.f;
            #pragma unroll
            for (int i = 0; i < 4; i++) {
                uint4 wq = wp[i * 32];
                acc0 += __uint_as_float(wq.x << 16)         * h[i*8+0];
                acc1 += __uint_as_float(wq.x & 0xFFFF0000u) * h[i*8+1];
                acc0 += __uint_as_float(wq.y << 16)         * h[i*8+2];
                acc1 += __uint_as_float(wq.y & 0xFFFF0000u) * h[i*8+3];
                acc0 += __uint_as_float(wq.z << 16)         * h[i*8+4];
                acc1 += __uint_as_float(wq.z & 0xFFFF0000u) * h[i*8+5];
                acc0 += __uint_as_float(wq.w << 16)         * h[i*8+6];
                acc1 += __uint_as_float(wq.w & 0xFFFF0000u) * h[i*8+7];
            }
            float acc = acc0 + acc1;
            #pragma unroll
            for (int s = 16; s > 0; s >>= 1)
                acc += __shfl_xor_sync(0xffffffffu, acc, s);
            if (l == 0) sacc[khalf * RMAX + r] = acc;     // no atomics
        }
        __syncthreads();

        // -- epilogue: gates -> (c, h) for this CTA's units -------------------
        if (tid < U) {
            float gi = sacc[0*U + tid] + sacc[RMAX + 0*U + tid] + xgi;
            float gf = sacc[1*U + tid] + sacc[RMAX + 1*U + tid] + xgf;
            float gg = sacc[2*U + tid] + sacc[RMAX + 2*U + tid] + xgg;
            float go = sacc[3*U + tid] + sacc[RMAX + 3*U + tid] + xgo;
            float ig = sigf(gi);
            float fg = sigf(gf);
            float gt = tanhf(gg);
            float og = sigf(go);
            c_state = fg * c_state + ig * gt;
            g_h[(t + 1) & 1][u0 + tid] = og * tanhf(c_state);
        }
        grid_barrier(b, (unsigned)(t + 2));
    }
}

__global__ void __launch_bounds__(NTHR) lstm_recurrent(const float* __restrict__ W_hh)
{
    const int b = blockIdx.x;
    if (b < 124) lstm_body<14>(b, b * 14, W_hh);
    else         lstm_body<13>(b, 124 * 14 + (b - 124) * 13, W_hh);
}

// ====================== Kernel 3: out = h_T @ W_lin^T + b_lin ===============
__global__ void __launch_bounds__(256) final_linear(
    const float* __restrict__ W_lin, const float* __restrict__ b_lin, float* out)
{
    __shared__ float red[256];
    float s = 0.f;
    // T_STEPS even -> final h lives in buffer 0
    for (int k = threadIdx.x; k < HSZ; k += 256)
        s += g_h[0][k] * W_lin[k];
    red[threadIdx.x] = s;
    __syncthreads();
    for (int o = 128; o > 0; o >>= 1) {
        if (threadIdx.x < o) red[threadIdx.x] += red[threadIdx.x + o];
        __syncthreads();
    }
    if (threadIdx.x == 0) out[0] = red[0] + b_lin[0];

    // reset barrier state so graph replays are deterministic
    if (threadIdx.x < 8) g_cnt[threadIdx.x * 32] = 0u;
    if (threadIdx.x == 0) g_go = 0u;
}

// ============================================================================
extern "C" void kernel_launch(void* const* d_in, const int* in_sizes, int n_in,
                              void* d_out, int out_size)
{
    const float* input = (const float*)d_in[0];
    const float* W_ih  = (const float*)d_in[1];
    const float* W_hh  = (const float*)d_in[2];
    const float* b_ih  = (const float*)d_in[3];
    const float* b_hh  = (const float*)d_in[4];
    const float* W_lin = (const float*)d_in[5];
    const float* b_lin = (const float*)d_in[6];

    dim3 g1(GSZ / BN, T_STEPS / BM);
    gemm_xgates<<<g1, 256>>>(input, W_ih, b_ih, b_hh);

    const int smem_bytes = RMAX * 1024 * 4 + 2 * RMAX * 4;   // 229,824 B
    cudaFuncSetAttribute(lstm_recurrent,
                         cudaFuncAttributeMaxDynamicSharedMemorySize, smem_bytes);
    lstm_recurrent<<<NBLK, NTHR, smem_bytes>>>(W_hh);

    final_linear<<<1, 256>>>(W_lin, b_lin, (float*)d_out);
}